// round 16
// baseline (speedup 1.0000x reference)
#include <cuda_runtime.h>
#include <cuda_bf16.h>
#include <cstdint>
#include <cstddef>

// Problem constants
#define PDIM 36
#define BB 4
#define NR 10
#define BN 40
#define RELD 7
#define RELC 256
#define LSTM 512
#define IMGF 2048
#define ROWS (BN*PDIM)          // 1440
#define RELROWS (BB*PDIM*PDIM)  // 5184
#define F2 (2*IMGF)             // 4096

// ===========================================================================
// Helpers
// ===========================================================================
__device__ __forceinline__ uint32_t smem_u32(const void* p) {
    uint32_t a;
    asm("{ .reg .u64 t; cvta.to.shared.u64 t, %1; cvt.u32.u64 %0, t; }" : "=r"(a) : "l"(p));
    return a;
}
__device__ __forceinline__ float sigmoidf_(float x) { return 1.0f / (1.0f + __expf(-x)); }
__device__ __forceinline__ void split2(float x, __nv_bfloat16& h, __nv_bfloat16& l) {
    h = __float2bfloat16(x);
    l = __float2bfloat16(x - __bfloat162float(h));
}
#define SWZ128(off) ((off) ^ (((off) >> 3) & 0x70))

__device__ __forceinline__ void cp_async16(uint32_t dst, const void* src, int szbytes) {
    asm volatile("cp.async.cg.shared.global [%0], [%1], 16, %2;"
                 :: "r"(dst), "l"(src), "r"(szbytes) : "memory");
}
#define CP_COMMIT() asm volatile("cp.async.commit_group;" ::: "memory")
#define CP_WAIT1()  asm volatile("cp.async.wait_group 1;" ::: "memory")
#define CP_WAIT0()  asm volatile("cp.async.wait_group 0;" ::: "memory")

__device__ __forceinline__ void ldm4(uint32_t* r, uint32_t a) {
    asm volatile("ldmatrix.sync.aligned.m8n8.x4.shared.b16 {%0,%1,%2,%3}, [%4];"
                 : "=r"(r[0]), "=r"(r[1]), "=r"(r[2]), "=r"(r[3]) : "r"(a));
}
__device__ __forceinline__ void mma16816(float* c, const uint32_t* a, uint32_t b0, uint32_t b1) {
    asm volatile("mma.sync.aligned.m16n8k16.row.col.f32.bf16.bf16.f32 "
                 "{%0,%1,%2,%3}, {%4,%5,%6,%7}, {%8,%9}, {%0,%1,%2,%3};"
                 : "+f"(c[0]), "+f"(c[1]), "+f"(c[2]), "+f"(c[3])
                 : "r"(a[0]), "r"(a[1]), "r"(a[2]), "r"(a[3]), "r"(b0), "r"(b1));
}

// ===========================================================================
// Scratch (device globals; no allocations allowed)
// ===========================================================================
__device__ float g_relS [RELROWS*RELC];
__device__ float g_relC [RELROWS*RELC];
__device__ float g_v    [BN*RELC];
__device__ float g_u    [BN*RELC];
__device__ float g_D2   [ROWS];
__device__ float g_gw   [ROWS*PDIM];
__device__ float g_cii  [ROWS*F2];
// split-K partial accumulators
__device__ float g_pimg [4*ROWS*RELC];                 // imgC split-K4 partials
__device__ float g_pout [2*(size_t)ROWS*IMGF];        // out split-K2 partials
// bf16 hi/lo operand splits
__device__ __nv_bfloat16 g_rSh[RELROWS*RELC], g_rSl[RELROWS*RELC];
__device__ __nv_bfloat16 g_iAh[ROWS*IMGF],    g_iAl[ROWS*IMGF];
__device__ __nv_bfloat16 g_cAh[(size_t)ROWS*F2], g_cAl[(size_t)ROWS*F2];
__device__ __nv_bfloat16 g_gAh[(size_t)ROWS*F2], g_gAl[(size_t)ROWS*F2];
__device__ __nv_bfloat16 g_B1h[RELC*RELC],    g_B1l[RELC*RELC];
__device__ __nv_bfloat16 g_B2h[RELC*IMGF],    g_B2l[RELC*IMGF];
__device__ __nv_bfloat16 g_Bwh[(size_t)F2*F2],   g_Bwl[(size_t)F2*F2];
__device__ __nv_bfloat16 g_Bih[(size_t)IMGF*F2], g_Bil[(size_t)IMGF*F2];

// ===========================================================================
// K1: relS = sigmoid(relation @ Wcr + bcr) + bf16 split
// ===========================================================================
__global__ void rels_kernel(const float* __restrict__ relation,
                            const float* __restrict__ Wcr,
                            const float* __restrict__ bcr)
{
    int r = blockIdx.x, c = threadIdx.x;
    __shared__ float rd[RELD];
    if (c < RELD) rd[c] = relation[r*RELD + c];
    __syncthreads();
    float acc = bcr[c];
#pragma unroll
    for (int d = 0; d < RELD; ++d) acc += rd[d] * Wcr[d*RELC + c];
    float s = sigmoidf_(acc);
    size_t idx = (size_t)r*RELC + c;
    g_relS[idx] = s;
    __nv_bfloat16 h, l; split2(s, h, l);
    g_rSh[idx] = h; g_rSl[idx] = l;
}

// ===========================================================================
// K2: question vectors
// ===========================================================================
__global__ void ques_kernel(const float* __restrict__ ques,
                            const float* __restrict__ Wq,
                            const float* __restrict__ bq,
                            const float* __restrict__ Wrw,
                            const float* __restrict__ Wg)
{
    int bn = blockIdx.x, c = threadIdx.x;
    __shared__ float q[LSTM];
    q[c] = ques[bn*LSTM + c];
    q[c + 256] = ques[bn*LSTM + c + 256];
    __syncthreads();
    float acc = bq[c];
    for (int k = 0; k < LSTM; ++k) acc += q[k] * Wq[k*RELC + c];
    float s = sigmoidf_(acc);
    g_v[bn*RELC + c] = s * Wrw[c];
    g_u[bn*RELC + c] = s * Wg[c];
}

// ===========================================================================
// tsplit body shared by convert kernels
// ===========================================================================
__device__ __forceinline__ void tsplit_body(const float* __restrict__ W, int K, int N,
                                            __nv_bfloat16* __restrict__ Bh,
                                            __nv_bfloat16* __restrict__ Bl,
                                            int bx, int by)
{
    __shared__ float tile[32][33];
    int tx = threadIdx.x & 31, ty = threadIdx.x >> 5;
    int n0 = bx * 32, k0 = by * 32;
#pragma unroll
    for (int r = 0; r < 4; ++r)
        tile[ty + r*8][tx] = W[(size_t)(k0 + ty + r*8) * N + n0 + tx];
    __syncthreads();
#pragma unroll
    for (int r = 0; r < 4; ++r) {
        int n = n0 + ty + r*8, k = k0 + tx;
        float v = tile[tx][ty + r*8];
        __nv_bfloat16 h, l; split2(v, h, l);
        Bh[(size_t)n*K + k] = h;
        Bl[(size_t)n*K + k] = l;
    }
}

// K3a: early conversions (img split + Wc1 + Wc2) — critical path for dual
__global__ void convert_early(const float* __restrict__ img, const float* __restrict__ Wc)
{
    int b = blockIdx.x;
    if (b < 2048) {
        size_t n = (size_t)ROWS*IMGF;
        for (size_t i = (size_t)b*256 + threadIdx.x; i < n; i += (size_t)2048*256) {
            __nv_bfloat16 h, l; split2(img[i], h, l);
            g_iAh[i] = h; g_iAl[i] = l;
        }
        return;
    }
    b -= 2048;
    if (b < 64) tsplit_body(Wc, RELC, RELC, g_B1h, g_B1l, b % 8, b / 8);
    else { b -= 64; tsplit_body(Wc + RELC*RELC, IMGF, RELC, g_B2h, g_B2l, b % 8, b / 8); }
}

// K3b: late conversions (Ww + Wi) — runs on side stream, hidden
__global__ void convert_wwwi(const float* __restrict__ Ww, const float* __restrict__ Wi)
{
    int b = blockIdx.x;
    if (b < 16384) tsplit_body(Ww, F2, F2, g_Bwh, g_Bwl, b % 128, b / 128);
    else { b -= 16384; tsplit_body(Wi, F2, IMGF, g_Bih, g_Bil, b % 64, b / 64); }
}

// ===========================================================================
// bf16-split GEMM tile body. CTA tile 128x128, BK=64, 16 warps 4x4 grid,
// 3-stage cp.async pipeline. nch = number of 64-wide K chunks to process;
// strideA/strideB = full row strides (split-K passes pointers offset to kbeg).
// EPI: 0 plain fp32, 2 sigmoid(acc+bias)*aux -> bf16 hi/lo
// ===========================================================================
#define STAGE_B 65536
#define NSTAGE 3
#define HG_SMEM (NSTAGE*STAGE_B)
#define GTHREADS 512

struct Frags {
    uint32_t ah[2][4];
    uint32_t al[2][4];
    uint32_t bh[2][4];
    uint32_t bl[2][4];
};

template<int EPI>
__device__ __forceinline__ void gemm_tile(
    int M, int N, int nch, int strideA, int strideB, int m0, int n0,
    const __nv_bfloat16* __restrict__ Ah, const __nv_bfloat16* __restrict__ Al,
    const __nv_bfloat16* __restrict__ Bh, const __nv_bfloat16* __restrict__ Bl,
    const float* __restrict__ bias, const float* __restrict__ aux,
    float* __restrict__ C,
    __nv_bfloat16* __restrict__ Ch, __nv_bfloat16* __restrict__ Cl,
    uint32_t sbase)
{
    const int tid = threadIdx.x;
    const int lid = tid & 31;
    const int wid = tid >> 5;       // 0..15
    const int wm = wid & 3;         // M strip (32 rows)
    const int wn = wid >> 2;        // N strip (32 cols)

    float acc[2][4][4];
#pragma unroll
    for (int i = 0; i < 2; ++i)
#pragma unroll
        for (int j = 0; j < 4; ++j)
#pragma unroll
            for (int e = 0; e < 4; ++e) acc[i][j][e] = 0.f;

    // loader mapping: 4 threads per 128B row, 2 x 16B segments each
    const int lrow = tid >> 2;           // 0..127
    const int lseg = (tid & 3) * 2;      // 0,2,4,6
    const int gmrow = m0 + lrow;
    const int a_ok = (gmrow < M) ? 16 : 0;
    const size_t aoff = (size_t)(a_ok ? gmrow : 0) * strideA;
    const size_t boff = (size_t)(n0 + lrow) * strideB;

    auto load_stage = [&](int c, int buf) {
        const int k0 = c << 6;
        const uint32_t sb = sbase + buf * STAGE_B;
        const char* pAh = (const char*)(Ah + aoff + k0);
        const char* pAl = (const char*)(Al + aoff + k0);
        const char* pBh = (const char*)(Bh + boff + k0);
        const char* pBl = (const char*)(Bl + boff + k0);
#pragma unroll
        for (int s = 0; s < 2; ++s) {
            const int colb = (lseg + s) * 16;
            const uint32_t sw = SWZ128((uint32_t)(lrow * 128 + colb));
            cp_async16(sb + sw,         pAh + colb, a_ok);
            cp_async16(sb + 16384 + sw, pAl + colb, a_ok);
            cp_async16(sb + 32768 + sw, pBh + colb, 16);
            cp_async16(sb + 49152 + sw, pBl + colb, 16);
        }
        CP_COMMIT();
    };

    // fragment lane components
    const int matA  = lid >> 3;
    const int rowA  = (lid & 7) + ((matA & 1) << 3);
    const int kselA = (matA >> 1) << 4;
    const int rowB  = (lid & 7) + ((matA >> 1) << 3);
    const int kselB = (matA & 1) << 4;

    auto load_frags = [&](uint32_t sb, int ks, Frags& F) {
        const int kb = ks << 5;
#pragma unroll
        for (int mi = 0; mi < 2; ++mi) {
            uint32_t off = SWZ128((uint32_t)((wm*32 + mi*16 + rowA) * 128 + kb + kselA));
            ldm4(F.ah[mi], sb + off);
            ldm4(F.al[mi], sb + 16384u + off);
        }
#pragma unroll
        for (int nb = 0; nb < 2; ++nb) {
            uint32_t off = SWZ128((uint32_t)((wn*32 + nb*16 + rowB) * 128 + kb + kselB));
            ldm4(F.bh[nb], sb + 32768u + off);
            ldm4(F.bl[nb], sb + 49152u + off);
        }
    };

    auto mma_all = [&](Frags& F) {
#pragma unroll
        for (int mi = 0; mi < 2; ++mi)
#pragma unroll
            for (int ni = 0; ni < 4; ++ni)
                mma16816(acc[mi][ni], F.ah[mi],
                         F.bh[ni >> 1][(ni & 1) * 2], F.bh[ni >> 1][(ni & 1) * 2 + 1]);
#pragma unroll
        for (int mi = 0; mi < 2; ++mi)
#pragma unroll
            for (int ni = 0; ni < 4; ++ni)
                mma16816(acc[mi][ni], F.ah[mi],
                         F.bl[ni >> 1][(ni & 1) * 2], F.bl[ni >> 1][(ni & 1) * 2 + 1]);
#pragma unroll
        for (int mi = 0; mi < 2; ++mi)
#pragma unroll
            for (int ni = 0; ni < 4; ++ni)
                mma16816(acc[mi][ni], F.al[mi],
                         F.bh[ni >> 1][(ni & 1) * 2], F.bh[ni >> 1][(ni & 1) * 2 + 1]);
    };

    load_stage(0, 0);
    if (nch > 1) load_stage(1, 1);
    for (int c = 0; c < nch; ++c) {
        if (c + 1 < nch) { CP_WAIT1(); } else { CP_WAIT0(); }
        __syncthreads();
        if (c + 2 < nch) load_stage(c + 2, (c + 2) % NSTAGE);
        const uint32_t sb = sbase + (c % NSTAGE) * STAGE_B;
#pragma unroll
        for (int ks = 0; ks < 4; ++ks) {
            Frags f;
            load_frags(sb, ks, f);
            mma_all(f);
        }
    }

    // epilogue
    const int er = lid >> 2;
    const int ec = (lid & 3) * 2;
#pragma unroll
    for (int mi = 0; mi < 2; ++mi) {
#pragma unroll
        for (int half = 0; half < 2; ++half) {
            const int gm = m0 + wm*32 + mi*16 + er + half*8;
            if (gm >= M) continue;
#pragma unroll
            for (int ni = 0; ni < 4; ++ni) {
                const int gn = n0 + wn*32 + ni*8 + ec;
                float v0 = acc[mi][ni][half*2 + 0];
                float v1 = acc[mi][ni][half*2 + 1];
                if (EPI == 0) {
                    float2 r; r.x = v0; r.y = v1;
                    *reinterpret_cast<float2*>(C + (size_t)gm*N + gn) = r;
                } else {
                    const size_t o = (size_t)gm*N + gn;
                    float g0 = sigmoidf_(v0 + bias[gn])     * aux[o];
                    float g1 = sigmoidf_(v1 + bias[gn + 1]) * aux[o + 1];
                    __nv_bfloat16 h0, l0, h1, l1;
                    split2(g0, h0, l0); split2(g1, h1, l1);
                    __nv_bfloat162 ph; ph.x = h0; ph.y = h1;
                    __nv_bfloat162 pl; pl.x = l0; pl.y = l1;
                    *reinterpret_cast<__nv_bfloat162*>(Ch + o) = ph;
                    *reinterpret_cast<__nv_bfloat162*>(Cl + o) = pl;
                }
            }
        }
    }
}

// gated GEMM (full-K, EPI2), M-offset for stream pipelining
__global__ __launch_bounds__(GTHREADS, 1)
void hgemm_gated(const __nv_bfloat16* __restrict__ Ah, const __nv_bfloat16* __restrict__ Al,
                 const __nv_bfloat16* __restrict__ Bh, const __nv_bfloat16* __restrict__ Bl,
                 const float* __restrict__ bias, const float* __restrict__ aux,
                 __nv_bfloat16* __restrict__ Ch, __nv_bfloat16* __restrict__ Cl,
                 int moff)
{
    extern __shared__ char sm[];
    gemm_tile<2>(ROWS, F2, F2/64, F2, F2, (blockIdx.y + moff) * 128, blockIdx.x * 128,
                 Ah, Al, Bh, Bl, bias, aux, nullptr, Ch, Cl, smem_u32(sm));
}

// out GEMM split-K2 partials (EPI0), M-offset
__global__ __launch_bounds__(GTHREADS, 1)
void hgemm_outk(const __nv_bfloat16* __restrict__ Ah, const __nv_bfloat16* __restrict__ Al,
                const __nv_bfloat16* __restrict__ Bh, const __nv_bfloat16* __restrict__ Bl,
                float* __restrict__ pout, int moff)
{
    extern __shared__ char sm[];
    const int part = blockIdx.z;
    const int kbeg = part * (F2/2);
    gemm_tile<0>(ROWS, IMGF, (F2/2)/64, F2, F2, (blockIdx.y + moff) * 128, blockIdx.x * 128,
                 Ah + kbeg, Al + kbeg, Bh + kbeg, Bl + kbeg,
                 nullptr, nullptr, pout + (size_t)part*ROWS*IMGF, nullptr, nullptr,
                 smem_u32(sm));
}

// Merged dual: blocks [0,96) imgC split-K4 partials, [96,178) relC GEMM
__global__ __launch_bounds__(GTHREADS, 1)
void hgemm_dual(const __nv_bfloat16* __restrict__ iAh, const __nv_bfloat16* __restrict__ iAl,
                const __nv_bfloat16* __restrict__ B2h, const __nv_bfloat16* __restrict__ B2l,
                float* __restrict__ pimg,
                const __nv_bfloat16* __restrict__ rSh, const __nv_bfloat16* __restrict__ rSl,
                const __nv_bfloat16* __restrict__ B1h, const __nv_bfloat16* __restrict__ B1l,
                float* __restrict__ relC)
{
    extern __shared__ char sm[];
    const uint32_t sbase = smem_u32(sm);
    int blk = blockIdx.x;
    if (blk < 96) {
        int part = blk / 24;           // 0..3, K quarter
        int sub  = blk % 24;
        int kbeg = part * (IMGF/4);    // 512
        gemm_tile<0>(ROWS, RELC, (IMGF/4)/64, IMGF, IMGF,
                     (sub >> 1) * 128, (sub & 1) * 128,
                     iAh + kbeg, iAl + kbeg, B2h + kbeg, B2l + kbeg,
                     nullptr, nullptr, pimg + (size_t)part*ROWS*RELC, nullptr, nullptr, sbase);
    } else {
        int idx = blk - 96;
        gemm_tile<0>(RELROWS, RELC, RELC/64, RELC, RELC,
                     (idx >> 1) * 128, (idx & 1) * 128,
                     rSh, rSl, B1h, B1l, nullptr, nullptr, relC, nullptr, nullptr, sbase);
    }
}

// ===========================================================================
// Fused: D2[row] = (sum4 pimg + bc) . u   (imgC never materialized)
// ===========================================================================
__global__ void d2_fused(const float* __restrict__ bc)
{
    int row = blockIdx.x, bn = row / PDIM, tid = threadIdx.x;
    size_t o = (size_t)row*RELC + tid;
    const size_t st = (size_t)ROWS*RELC;
    float val = g_pimg[o] + g_pimg[o + st] + g_pimg[o + 2*st] + g_pimg[o + 3*st] + bc[tid];
    float p = val * g_u[bn*RELC + tid];
    __shared__ float sr[8];
#pragma unroll
    for (int off = 16; off; off >>= 1) p += __shfl_xor_sync(0xffffffffu, p, off);
    if ((tid & 31) == 0) sr[tid >> 5] = p;
    __syncthreads();
    if (tid == 0) {
        float s = 0.f;
#pragma unroll
        for (int k = 0; k < 8; ++k) s += sr[k];
        g_D2[row] = s;
    }
}

__global__ void reduce_out(const float* __restrict__ bi, float* __restrict__ out)
{
    const size_t n = (size_t)ROWS*IMGF;
    const size_t st = n;
    for (size_t i = (size_t)blockIdx.x*blockDim.x + threadIdx.x; i < n;
         i += (size_t)gridDim.x*blockDim.x) {
        out[i] = g_pout[i] + g_pout[i + st] + bi[i & (IMGF-1)];
    }
}

// ===========================================================================
// K5: per (bn,i): rw softmax -> gw softmax
// ===========================================================================
__global__ void gw_kernel()
{
    int blk = blockIdx.x;
    int bn = blk / PDIM, i = blk % PDIM;
    int b = bn / NR, m = bn % NR;
    int tid = threadIdx.x;
    int w = tid >> 5, lane = tid & 31;
    __shared__ float sL[PDIM], sD[PDIM], sred[2];
    const float* vv = g_v + bn*RELC;
    const float* uu = g_u + bn*RELC;

    for (int j = w; j < PDIM; j += 4) {
        int R  = m*(PDIM*PDIM) + i*PDIM + j;
        int si = R / (NR*PDIM);
        size_t rowbase = ((size_t)b*PDIM*PDIM + (size_t)si*PDIM + j) * RELC;
        const float* rs = g_relS + rowbase;
        const float* rc = g_relC + rowbase;
        float s1 = 0.f, s2 = 0.f;
        for (int c = lane; c < RELC; c += 32) { s1 += rs[c]*vv[c]; s2 += rc[c]*uu[c]; }
#pragma unroll
        for (int off = 16; off; off >>= 1) {
            s1 += __shfl_xor_sync(0xffffffffu, s1, off);
            s2 += __shfl_xor_sync(0xffffffffu, s2, off);
        }
        if (lane == 0) { sL[j] = s1; sD[j] = s2; }
    }
    __syncthreads();
    if (tid == 0) { float mx = -1e30f; for (int j=0;j<PDIM;++j) mx = fmaxf(mx, sL[j]); sred[0] = mx; }
    __syncthreads();
    if (tid < PDIM) sL[tid] = __expf(sL[tid] - sred[0]);
    __syncthreads();
    if (tid == 0) { float s = 0.f; for (int j=0;j<PDIM;++j) s += sL[j]; sred[1] = 1.0f/s; }
    __syncthreads();
    if (tid < PDIM) sL[tid] = sL[tid]*sred[1]*sD[tid] + g_D2[bn*PDIM + tid];
    __syncthreads();
    if (tid == 0) { float mx = -1e30f; for (int j=0;j<PDIM;++j) mx = fmaxf(mx, sL[j]); sred[0] = mx; }
    __syncthreads();
    if (tid < PDIM) sL[tid] = __expf(sL[tid] - sred[0]);
    __syncthreads();
    if (tid == 0) { float s = 0.f; for (int j=0;j<PDIM;++j) s += sL[j]; sred[1] = 1.0f/s; }
    __syncthreads();
    if (tid < PDIM) g_gw[(size_t)blk*PDIM + tid] = sL[tid]*sred[1];
}

// ===========================================================================
// K6: img_ws + assemble cii (fp32) + bf16 split of cii
// ===========================================================================
__global__ void imgws_kernel(const float* __restrict__ img)
{
    int chunk = blockIdx.x, bn = blockIdx.y, tid = threadIdx.x;
    __shared__ float sg[PDIM*PDIM];
    for (int t = tid; t < PDIM*PDIM; t += 256) sg[t] = g_gw[(size_t)bn*PDIM*PDIM + t];
    __syncthreads();

    int f = chunk*256 + tid;
    float acc[PDIM];
#pragma unroll
    for (int i = 0; i < PDIM; ++i) acc[i] = 0.f;
    const float* ib = img + (size_t)bn*PDIM*IMGF + f;
#pragma unroll 4
    for (int j = 0; j < PDIM; ++j) {
        float vj = ib[(size_t)j*IMGF];
#pragma unroll
        for (int i = 0; i < PDIM; ++i) acc[i] += sg[i*PDIM + j] * vj;
    }
    size_t cb = (size_t)bn*PDIM*F2 + f;
#pragma unroll
    for (int i = 0; i < PDIM; ++i) {
        float iv = ib[(size_t)i*IMGF];
        size_t o0 = cb + (size_t)i*F2;
        size_t o1 = o0 + IMGF;
        g_cii[o0] = iv;
        g_cii[o1] = acc[i];
        __nv_bfloat16 h, l;
        split2(iv, h, l);     g_cAh[o0] = h; g_cAl[o0] = l;
        split2(acc[i], h, l); g_cAh[o1] = h; g_cAl[o1] = l;
    }
}

// ===========================================================================
// Launch — two-stream choreography (fork/join via events, capture-safe)
// ===========================================================================
extern "C" void kernel_launch(void* const* d_in, const int* in_sizes, int n_in,
                              void* d_out, int out_size)
{
    const float* relation = (const float*)d_in[0];
    const float* img      = (const float*)d_in[1];
    const float* ques     = (const float*)d_in[2];
    const float* Wcr      = (const float*)d_in[3];
    const float* bcr      = (const float*)d_in[4];
    const float* Wq       = (const float*)d_in[5];
    const float* bq       = (const float*)d_in[6];
    const float* Wrw      = (const float*)d_in[7];
    const float* Wc       = (const float*)d_in[9];
    const float* bc       = (const float*)d_in[10];
    const float* Wg       = (const float*)d_in[11];
    const float* Ww       = (const float*)d_in[13];
    const float* bw       = (const float*)d_in[14];
    const float* Wi       = (const float*)d_in[15];
    const float* bi       = (const float*)d_in[16];
    float* out = (float*)d_out;

    // one-time resources (created on first, uncaptured, correctness call)
    static cudaStream_t s2 = nullptr;
    static cudaEvent_t ev0 = nullptr, evW = nullptr, evI = nullptr, ev2 = nullptr;
    if (!s2) {
        cudaStreamCreateWithFlags(&s2, cudaStreamNonBlocking);
        cudaEventCreateWithFlags(&ev0, cudaEventDisableTiming);
        cudaEventCreateWithFlags(&evW, cudaEventDisableTiming);
        cudaEventCreateWithFlags(&evI, cudaEventDisableTiming);
        cudaEventCreateWithFlags(&ev2, cudaEventDisableTiming);
        cudaFuncSetAttribute(hgemm_gated, cudaFuncAttributeMaxDynamicSharedMemorySize, HG_SMEM);
        cudaFuncSetAttribute(hgemm_outk,  cudaFuncAttributeMaxDynamicSharedMemorySize, HG_SMEM);
        cudaFuncSetAttribute(hgemm_dual,  cudaFuncAttributeMaxDynamicSharedMemorySize, HG_SMEM);
    }

    float *p_relC, *p_pimg, *p_pout, *p_cii;
    __nv_bfloat16 *p_rSh,*p_rSl,*p_iAh,*p_iAl,*p_cAh,*p_cAl,*p_gAh,*p_gAl;
    __nv_bfloat16 *p_B1h,*p_B1l,*p_B2h,*p_B2l,*p_Bwh,*p_Bwl,*p_Bih,*p_Bil;
    cudaGetSymbolAddress((void**)&p_relC, g_relC);
    cudaGetSymbolAddress((void**)&p_pimg, g_pimg);
    cudaGetSymbolAddress((void**)&p_pout, g_pout);
    cudaGetSymbolAddress((void**)&p_cii,  g_cii);
    cudaGetSymbolAddress((void**)&p_rSh, g_rSh); cudaGetSymbolAddress((void**)&p_rSl, g_rSl);
    cudaGetSymbolAddress((void**)&p_iAh, g_iAh); cudaGetSymbolAddress((void**)&p_iAl, g_iAl);
    cudaGetSymbolAddress((void**)&p_cAh, g_cAh); cudaGetSymbolAddress((void**)&p_cAl, g_cAl);
    cudaGetSymbolAddress((void**)&p_gAh, g_gAh); cudaGetSymbolAddress((void**)&p_gAl, g_gAl);
    cudaGetSymbolAddress((void**)&p_B1h, g_B1h); cudaGetSymbolAddress((void**)&p_B1l, g_B1l);
    cudaGetSymbolAddress((void**)&p_B2h, g_B2h); cudaGetSymbolAddress((void**)&p_B2l, g_B2l);
    cudaGetSymbolAddress((void**)&p_Bwh, g_Bwh); cudaGetSymbolAddress((void**)&p_Bwl, g_Bwl);
    cudaGetSymbolAddress((void**)&p_Bih, g_Bih); cudaGetSymbolAddress((void**)&p_Bil, g_Bil);

    // ---- fork: heavy weight conversion on s2 (hidden under legacy chain)
    cudaEventRecord(ev0, 0);
    cudaStreamWaitEvent(s2, ev0, 0);
    convert_wwwi<<<16384 + 8192, 256, 0, s2>>>(Ww, Wi);
    cudaEventRecord(evW, s2);

    // ---- legacy chain
    rels_kernel<<<RELROWS, RELC>>>(relation, Wcr, bcr);
    ques_kernel<<<BN, RELC>>>(ques, Wq, bq, Wrw, Wg);
    convert_early<<<2048 + 64 + 512, 256>>>(img, Wc);
    hgemm_dual<<<178, GTHREADS, HG_SMEM>>>(p_iAh, p_iAl, p_B2h, p_B2l, p_pimg,
                                           p_rSh, p_rSl, p_B1h, p_B1l, p_relC);
    d2_fused<<<ROWS, RELC>>>(bc);
    gw_kernel<<<ROWS, 128>>>();
    imgws_kernel<<<dim3(IMGF/256, BN), 256>>>(img);
    cudaEventRecord(evI, 0);

    // ---- M-split pipelines: legacy does rows [0,768), s2 does rows [768,1440)
    cudaStreamWaitEvent(0, evW, 0);
    hgemm_gated<<<dim3(F2/128, 6), GTHREADS, HG_SMEM>>>(
        p_cAh, p_cAl, p_Bwh, p_Bwl, bw, p_cii, p_gAh, p_gAl, 0);

    cudaStreamWaitEvent(s2, evI, 0);
    hgemm_gated<<<dim3(F2/128, 6), GTHREADS, HG_SMEM, s2>>>(
        p_cAh, p_cAl, p_Bwh, p_Bwl, bw, p_cii, p_gAh, p_gAl, 6);

    hgemm_outk<<<dim3(IMGF/128, 6, 2), GTHREADS, HG_SMEM>>>(
        p_gAh, p_gAl, p_Bih, p_Bil, p_pout, 0);

    hgemm_outk<<<dim3(IMGF/128, 6, 2), GTHREADS, HG_SMEM, s2>>>(
        p_gAh, p_gAl, p_Bih, p_Bil, p_pout, 6);
    cudaEventRecord(ev2, s2);

    // ---- join + final reduce
    cudaStreamWaitEvent(0, ev2, 0);
    reduce_out<<<4096, 256>>>(bi, out);
}

// round 17
// speedup vs baseline: 1.4097x; 1.4097x over previous
#include <cuda_runtime.h>
#include <cuda_bf16.h>
#include <cstdint>
#include <cstddef>

// Problem constants
#define PDIM 36
#define BB 4
#define NR 10
#define BN 40
#define RELD 7
#define RELC 256
#define LSTM 512
#define IMGF 2048
#define ROWS (BN*PDIM)          // 1440
#define RELROWS (BB*PDIM*PDIM)  // 5184
#define F2 (2*IMGF)             // 4096

// ===========================================================================
// Helpers
// ===========================================================================
__device__ __forceinline__ uint32_t smem_u32(const void* p) {
    uint32_t a;
    asm("{ .reg .u64 t; cvta.to.shared.u64 t, %1; cvt.u32.u64 %0, t; }" : "=r"(a) : "l"(p));
    return a;
}
__device__ __forceinline__ float sigmoidf_(float x) { return 1.0f / (1.0f + __expf(-x)); }
__device__ __forceinline__ void split2(float x, __nv_bfloat16& h, __nv_bfloat16& l) {
    h = __float2bfloat16(x);
    l = __float2bfloat16(x - __bfloat162float(h));
}
#define SWZ128(off) ((off) ^ (((off) >> 3) & 0x70))

__device__ __forceinline__ void cp_async16(uint32_t dst, const void* src, int szbytes) {
    asm volatile("cp.async.cg.shared.global [%0], [%1], 16, %2;"
                 :: "r"(dst), "l"(src), "r"(szbytes) : "memory");
}
#define CP_COMMIT() asm volatile("cp.async.commit_group;" ::: "memory")
#define CP_WAIT1()  asm volatile("cp.async.wait_group 1;" ::: "memory")
#define CP_WAIT0()  asm volatile("cp.async.wait_group 0;" ::: "memory")

__device__ __forceinline__ void ldm4(uint32_t* r, uint32_t a) {
    asm volatile("ldmatrix.sync.aligned.m8n8.x4.shared.b16 {%0,%1,%2,%3}, [%4];"
                 : "=r"(r[0]), "=r"(r[1]), "=r"(r[2]), "=r"(r[3]) : "r"(a));
}
__device__ __forceinline__ void mma16816(float* c, const uint32_t* a, uint32_t b0, uint32_t b1) {
    asm volatile("mma.sync.aligned.m16n8k16.row.col.f32.bf16.bf16.f32 "
                 "{%0,%1,%2,%3}, {%4,%5,%6,%7}, {%8,%9}, {%0,%1,%2,%3};"
                 : "+f"(c[0]), "+f"(c[1]), "+f"(c[2]), "+f"(c[3])
                 : "r"(a[0]), "r"(a[1]), "r"(a[2]), "r"(a[3]), "r"(b0), "r"(b1));
}

// ===========================================================================
// Scratch (device globals; no allocations allowed)
// ===========================================================================
__device__ float g_relS [RELROWS*RELC];
__device__ float g_relC [RELROWS*RELC];
__device__ float g_v    [BN*RELC];
__device__ float g_u    [BN*RELC];
__device__ float g_D2   [ROWS];
__device__ float g_gw   [ROWS*PDIM];
__device__ float g_cii  [ROWS*F2];
// split-K partial accumulators
__device__ float g_pimg [4*ROWS*RELC];                 // imgC split-K4 partials
__device__ float g_pout [2*(size_t)ROWS*IMGF];        // out split-K2 partials
// bf16 hi/lo operand splits
__device__ __nv_bfloat16 g_rSh[RELROWS*RELC], g_rSl[RELROWS*RELC];
__device__ __nv_bfloat16 g_iAh[ROWS*IMGF],    g_iAl[ROWS*IMGF];
__device__ __nv_bfloat16 g_cAh[(size_t)ROWS*F2], g_cAl[(size_t)ROWS*F2];
__device__ __nv_bfloat16 g_gAh[(size_t)ROWS*F2], g_gAl[(size_t)ROWS*F2];
__device__ __nv_bfloat16 g_B1h[RELC*RELC],    g_B1l[RELC*RELC];
__device__ __nv_bfloat16 g_B2h[RELC*IMGF],    g_B2l[RELC*IMGF];
__device__ __nv_bfloat16 g_Bwh[(size_t)F2*F2],   g_Bwl[(size_t)F2*F2];
__device__ __nv_bfloat16 g_Bih[(size_t)IMGF*F2], g_Bil[(size_t)IMGF*F2];

// ===========================================================================
// tsplit body (weight transpose + bf16 hi/lo split)
// ===========================================================================
__device__ __forceinline__ void tsplit_body(const float* __restrict__ W, int K, int N,
                                            __nv_bfloat16* __restrict__ Bh,
                                            __nv_bfloat16* __restrict__ Bl,
                                            int bx, int by)
{
    __shared__ float tile[32][33];
    int tx = threadIdx.x & 31, ty = threadIdx.x >> 5;
    int n0 = bx * 32, k0 = by * 32;
#pragma unroll
    for (int r = 0; r < 4; ++r)
        tile[ty + r*8][tx] = W[(size_t)(k0 + ty + r*8) * N + n0 + tx];
    __syncthreads();
#pragma unroll
    for (int r = 0; r < 4; ++r) {
        int n = n0 + ty + r*8, k = k0 + tx;
        float v = tile[tx][ty + r*8];
        __nv_bfloat16 h, l; split2(v, h, l);
        Bh[(size_t)n*K + k] = h;
        Bl[(size_t)n*K + k] = l;
    }
}

// ===========================================================================
// K1 (mega preprocessing): rels + ques + img split + all 4 weight tsplits.
// All jobs independent; 256 threads/block; job selected by blockIdx.
// Layout: [0,5184) rels | [5184,5224) ques | [5224,7272) img
//         | +64 Wc1 | +512 Wc2 | +16384 Ww | +8192 Wi
// ===========================================================================
#define PRE_RELS   0
#define PRE_QUES   (PRE_RELS + RELROWS)          // 5184
#define PRE_IMG    (PRE_QUES + BN)               // 5224
#define PRE_WC1    (PRE_IMG + 2048)              // 7272
#define PRE_WC2    (PRE_WC1 + 64)
#define PRE_WW     (PRE_WC2 + 512)
#define PRE_WI     (PRE_WW + 16384)
#define PRE_TOTAL  (PRE_WI + 8192)

__global__ void preprocess_all(const float* __restrict__ relation,
                               const float* __restrict__ Wcr,
                               const float* __restrict__ bcr,
                               const float* __restrict__ ques,
                               const float* __restrict__ Wq,
                               const float* __restrict__ bq,
                               const float* __restrict__ Wrw,
                               const float* __restrict__ Wg,
                               const float* __restrict__ img,
                               const float* __restrict__ Wc,
                               const float* __restrict__ Ww,
                               const float* __restrict__ Wi)
{
    int b = blockIdx.x;
    if (b < PRE_QUES) {
        // rels: sigmoid(relation @ Wcr + bcr) + bf16 split
        int r = b, c = threadIdx.x;
        __shared__ float rd[RELD];
        if (c < RELD) rd[c] = relation[r*RELD + c];
        __syncthreads();
        float acc = bcr[c];
#pragma unroll
        for (int d = 0; d < RELD; ++d) acc += rd[d] * Wcr[d*RELC + c];
        float s = sigmoidf_(acc);
        size_t idx = (size_t)r*RELC + c;
        g_relS[idx] = s;
        __nv_bfloat16 h, l; split2(s, h, l);
        g_rSh[idx] = h; g_rSl[idx] = l;
        return;
    }
    if (b < PRE_IMG) {
        // ques vectors
        int bn = b - PRE_QUES, c = threadIdx.x;
        __shared__ float q[LSTM];
        q[c] = ques[bn*LSTM + c];
        q[c + 256] = ques[bn*LSTM + c + 256];
        __syncthreads();
        float acc = bq[c];
        for (int k = 0; k < LSTM; ++k) acc += q[k] * Wq[k*RELC + c];
        float s = sigmoidf_(acc);
        g_v[bn*RELC + c] = s * Wrw[c];
        g_u[bn*RELC + c] = s * Wg[c];
        return;
    }
    if (b < PRE_WC1) {
        int bb = b - PRE_IMG;
        size_t n = (size_t)ROWS*IMGF;
        for (size_t i = (size_t)bb*256 + threadIdx.x; i < n; i += (size_t)2048*256) {
            __nv_bfloat16 h, l; split2(img[i], h, l);
            g_iAh[i] = h; g_iAl[i] = l;
        }
        return;
    }
    if (b < PRE_WC2) { int bb = b - PRE_WC1; tsplit_body(Wc, RELC, RELC, g_B1h, g_B1l, bb % 8, bb / 8); return; }
    if (b < PRE_WW)  { int bb = b - PRE_WC2; tsplit_body(Wc + RELC*RELC, IMGF, RELC, g_B2h, g_B2l, bb % 8, bb / 8); return; }
    if (b < PRE_WI)  { int bb = b - PRE_WW;  tsplit_body(Ww, F2, F2, g_Bwh, g_Bwl, bb % 128, bb / 128); return; }
    { int bb = b - PRE_WI; tsplit_body(Wi, F2, IMGF, g_Bih, g_Bil, bb % 64, bb / 64); }
}

// ===========================================================================
// bf16-split GEMM tile body. CTA tile 128x128, BK=64, 16 warps 4x4 grid,
// 3-stage cp.async pipeline. nch = number of 64-wide K chunks to process;
// strideA/strideB = full row strides (split-K passes pointers offset to kbeg).
// EPI: 0 plain fp32, 2 sigmoid(acc+bias)*aux -> bf16 hi/lo
// ===========================================================================
#define STAGE_B 65536
#define NSTAGE 3
#define HG_SMEM (NSTAGE*STAGE_B)
#define GTHREADS 512

struct Frags {
    uint32_t ah[2][4];
    uint32_t al[2][4];
    uint32_t bh[2][4];
    uint32_t bl[2][4];
};

template<int EPI>
__device__ __forceinline__ void gemm_tile(
    int M, int N, int nch, int strideA, int strideB, int m0, int n0,
    const __nv_bfloat16* __restrict__ Ah, const __nv_bfloat16* __restrict__ Al,
    const __nv_bfloat16* __restrict__ Bh, const __nv_bfloat16* __restrict__ Bl,
    const float* __restrict__ bias, const float* __restrict__ aux,
    float* __restrict__ C,
    __nv_bfloat16* __restrict__ Ch, __nv_bfloat16* __restrict__ Cl,
    uint32_t sbase)
{
    const int tid = threadIdx.x;
    const int lid = tid & 31;
    const int wid = tid >> 5;       // 0..15
    const int wm = wid & 3;         // M strip (32 rows)
    const int wn = wid >> 2;        // N strip (32 cols)

    float acc[2][4][4];
#pragma unroll
    for (int i = 0; i < 2; ++i)
#pragma unroll
        for (int j = 0; j < 4; ++j)
#pragma unroll
            for (int e = 0; e < 4; ++e) acc[i][j][e] = 0.f;

    // loader mapping: 4 threads per 128B row, 2 x 16B segments each
    const int lrow = tid >> 2;           // 0..127
    const int lseg = (tid & 3) * 2;      // 0,2,4,6
    const int gmrow = m0 + lrow;
    const int a_ok = (gmrow < M) ? 16 : 0;
    const size_t aoff = (size_t)(a_ok ? gmrow : 0) * strideA;
    const size_t boff = (size_t)(n0 + lrow) * strideB;

    auto load_stage = [&](int c, int buf) {
        const int k0 = c << 6;
        const uint32_t sb = sbase + buf * STAGE_B;
        const char* pAh = (const char*)(Ah + aoff + k0);
        const char* pAl = (const char*)(Al + aoff + k0);
        const char* pBh = (const char*)(Bh + boff + k0);
        const char* pBl = (const char*)(Bl + boff + k0);
#pragma unroll
        for (int s = 0; s < 2; ++s) {
            const int colb = (lseg + s) * 16;
            const uint32_t sw = SWZ128((uint32_t)(lrow * 128 + colb));
            cp_async16(sb + sw,         pAh + colb, a_ok);
            cp_async16(sb + 16384 + sw, pAl + colb, a_ok);
            cp_async16(sb + 32768 + sw, pBh + colb, 16);
            cp_async16(sb + 49152 + sw, pBl + colb, 16);
        }
        CP_COMMIT();
    };

    // fragment lane components
    const int matA  = lid >> 3;
    const int rowA  = (lid & 7) + ((matA & 1) << 3);
    const int kselA = (matA >> 1) << 4;
    const int rowB  = (lid & 7) + ((matA >> 1) << 3);
    const int kselB = (matA & 1) << 4;

    auto load_frags = [&](uint32_t sb, int ks, Frags& F) {
        const int kb = ks << 5;
#pragma unroll
        for (int mi = 0; mi < 2; ++mi) {
            uint32_t off = SWZ128((uint32_t)((wm*32 + mi*16 + rowA) * 128 + kb + kselA));
            ldm4(F.ah[mi], sb + off);
            ldm4(F.al[mi], sb + 16384u + off);
        }
#pragma unroll
        for (int nb = 0; nb < 2; ++nb) {
            uint32_t off = SWZ128((uint32_t)((wn*32 + nb*16 + rowB) * 128 + kb + kselB));
            ldm4(F.bh[nb], sb + 32768u + off);
            ldm4(F.bl[nb], sb + 49152u + off);
        }
    };

    auto mma_all = [&](Frags& F) {
#pragma unroll
        for (int mi = 0; mi < 2; ++mi)
#pragma unroll
            for (int ni = 0; ni < 4; ++ni)
                mma16816(acc[mi][ni], F.ah[mi],
                         F.bh[ni >> 1][(ni & 1) * 2], F.bh[ni >> 1][(ni & 1) * 2 + 1]);
#pragma unroll
        for (int mi = 0; mi < 2; ++mi)
#pragma unroll
            for (int ni = 0; ni < 4; ++ni)
                mma16816(acc[mi][ni], F.ah[mi],
                         F.bl[ni >> 1][(ni & 1) * 2], F.bl[ni >> 1][(ni & 1) * 2 + 1]);
#pragma unroll
        for (int mi = 0; mi < 2; ++mi)
#pragma unroll
            for (int ni = 0; ni < 4; ++ni)
                mma16816(acc[mi][ni], F.al[mi],
                         F.bh[ni >> 1][(ni & 1) * 2], F.bh[ni >> 1][(ni & 1) * 2 + 1]);
    };

    load_stage(0, 0);
    if (nch > 1) load_stage(1, 1);
    for (int c = 0; c < nch; ++c) {
        if (c + 1 < nch) { CP_WAIT1(); } else { CP_WAIT0(); }
        __syncthreads();
        if (c + 2 < nch) load_stage(c + 2, (c + 2) % NSTAGE);
        const uint32_t sb = sbase + (c % NSTAGE) * STAGE_B;
#pragma unroll
        for (int ks = 0; ks < 4; ++ks) {
            Frags f;
            load_frags(sb, ks, f);
            mma_all(f);
        }
    }

    // epilogue
    const int er = lid >> 2;
    const int ec = (lid & 3) * 2;
#pragma unroll
    for (int mi = 0; mi < 2; ++mi) {
#pragma unroll
        for (int half = 0; half < 2; ++half) {
            const int gm = m0 + wm*32 + mi*16 + er + half*8;
            if (gm >= M) continue;
#pragma unroll
            for (int ni = 0; ni < 4; ++ni) {
                const int gn = n0 + wn*32 + ni*8 + ec;
                float v0 = acc[mi][ni][half*2 + 0];
                float v1 = acc[mi][ni][half*2 + 1];
                if (EPI == 0) {
                    float2 r; r.x = v0; r.y = v1;
                    *reinterpret_cast<float2*>(C + (size_t)gm*N + gn) = r;
                } else {
                    const size_t o = (size_t)gm*N + gn;
                    float g0 = sigmoidf_(v0 + bias[gn])     * aux[o];
                    float g1 = sigmoidf_(v1 + bias[gn + 1]) * aux[o + 1];
                    __nv_bfloat16 h0, l0, h1, l1;
                    split2(g0, h0, l0); split2(g1, h1, l1);
                    __nv_bfloat162 ph; ph.x = h0; ph.y = h1;
                    __nv_bfloat162 pl; pl.x = l0; pl.y = l1;
                    *reinterpret_cast<__nv_bfloat162*>(Ch + o) = ph;
                    *reinterpret_cast<__nv_bfloat162*>(Cl + o) = pl;
                }
            }
        }
    }
}

// gated GEMM (full-K, EPI2)
__global__ __launch_bounds__(GTHREADS, 1)
void hgemm_gated(const __nv_bfloat16* __restrict__ Ah, const __nv_bfloat16* __restrict__ Al,
                 const __nv_bfloat16* __restrict__ Bh, const __nv_bfloat16* __restrict__ Bl,
                 const float* __restrict__ bias, const float* __restrict__ aux,
                 __nv_bfloat16* __restrict__ Ch, __nv_bfloat16* __restrict__ Cl)
{
    extern __shared__ char sm[];
    gemm_tile<2>(ROWS, F2, F2/64, F2, F2, blockIdx.y * 128, blockIdx.x * 128,
                 Ah, Al, Bh, Bl, bias, aux, nullptr, Ch, Cl, smem_u32(sm));
}

// out GEMM split-K2: blockIdx.z = K half; writes fp32 partials (EPI0)
__global__ __launch_bounds__(GTHREADS, 1)
void hgemm_outk(const __nv_bfloat16* __restrict__ Ah, const __nv_bfloat16* __restrict__ Al,
                const __nv_bfloat16* __restrict__ Bh, const __nv_bfloat16* __restrict__ Bl,
                float* __restrict__ pout)
{
    extern __shared__ char sm[];
    const int part = blockIdx.z;
    const int kbeg = part * (F2/2);
    gemm_tile<0>(ROWS, IMGF, (F2/2)/64, F2, F2, blockIdx.y * 128, blockIdx.x * 128,
                 Ah + kbeg, Al + kbeg, Bh + kbeg, Bl + kbeg,
                 nullptr, nullptr, pout + (size_t)part*ROWS*IMGF, nullptr, nullptr,
                 smem_u32(sm));
}

// Merged dual: blocks [0,96) imgC split-K4 partials, [96,178) relC GEMM
__global__ __launch_bounds__(GTHREADS, 1)
void hgemm_dual(const __nv_bfloat16* __restrict__ iAh, const __nv_bfloat16* __restrict__ iAl,
                const __nv_bfloat16* __restrict__ B2h, const __nv_bfloat16* __restrict__ B2l,
                float* __restrict__ pimg,
                const __nv_bfloat16* __restrict__ rSh, const __nv_bfloat16* __restrict__ rSl,
                const __nv_bfloat16* __restrict__ B1h, const __nv_bfloat16* __restrict__ B1l,
                float* __restrict__ relC)
{
    extern __shared__ char sm[];
    const uint32_t sbase = smem_u32(sm);
    int blk = blockIdx.x;
    if (blk < 96) {
        int part = blk / 24;           // 0..3, K quarter
        int sub  = blk % 24;
        int kbeg = part * (IMGF/4);    // 512
        gemm_tile<0>(ROWS, RELC, (IMGF/4)/64, IMGF, IMGF,
                     (sub >> 1) * 128, (sub & 1) * 128,
                     iAh + kbeg, iAl + kbeg, B2h + kbeg, B2l + kbeg,
                     nullptr, nullptr, pimg + (size_t)part*ROWS*RELC, nullptr, nullptr, sbase);
    } else {
        int idx = blk - 96;
        gemm_tile<0>(RELROWS, RELC, RELC/64, RELC, RELC,
                     (idx >> 1) * 128, (idx & 1) * 128,
                     rSh, rSl, B1h, B1l, nullptr, nullptr, relC, nullptr, nullptr, sbase);
    }
}

// ===========================================================================
// Fused: D2[row] = (sum4 pimg + bc) . u   (imgC never materialized)
// ===========================================================================
__global__ void d2_fused(const float* __restrict__ bc)
{
    int row = blockIdx.x, bn = row / PDIM, tid = threadIdx.x;
    size_t o = (size_t)row*RELC + tid;
    const size_t st = (size_t)ROWS*RELC;
    float val = g_pimg[o] + g_pimg[o + st] + g_pimg[o + 2*st] + g_pimg[o + 3*st] + bc[tid];
    float p = val * g_u[bn*RELC + tid];
    __shared__ float sr[8];
#pragma unroll
    for (int off = 16; off; off >>= 1) p += __shfl_xor_sync(0xffffffffu, p, off);
    if ((tid & 31) == 0) sr[tid >> 5] = p;
    __syncthreads();
    if (tid == 0) {
        float s = 0.f;
#pragma unroll
        for (int k = 0; k < 8; ++k) s += sr[k];
        g_D2[row] = s;
    }
}

__global__ void reduce_out(const float* __restrict__ bi, float* __restrict__ out)
{
    const size_t n = (size_t)ROWS*IMGF;
    const size_t st = n;
    for (size_t i = (size_t)blockIdx.x*blockDim.x + threadIdx.x; i < n;
         i += (size_t)gridDim.x*blockDim.x) {
        out[i] = g_pout[i] + g_pout[i + st] + bi[i & (IMGF-1)];
    }
}

// ===========================================================================
// K5: per (bn,i): rw softmax -> gw softmax
// ===========================================================================
__global__ void gw_kernel()
{
    int blk = blockIdx.x;
    int bn = blk / PDIM, i = blk % PDIM;
    int b = bn / NR, m = bn % NR;
    int tid = threadIdx.x;
    int w = tid >> 5, lane = tid & 31;
    __shared__ float sL[PDIM], sD[PDIM], sred[2];
    const float* vv = g_v + bn*RELC;
    const float* uu = g_u + bn*RELC;

    for (int j = w; j < PDIM; j += 4) {
        int R  = m*(PDIM*PDIM) + i*PDIM + j;
        int si = R / (NR*PDIM);
        size_t rowbase = ((size_t)b*PDIM*PDIM + (size_t)si*PDIM + j) * RELC;
        const float* rs = g_relS + rowbase;
        const float* rc = g_relC + rowbase;
        float s1 = 0.f, s2 = 0.f;
        for (int c = lane; c < RELC; c += 32) { s1 += rs[c]*vv[c]; s2 += rc[c]*uu[c]; }
#pragma unroll
        for (int off = 16; off; off >>= 1) {
            s1 += __shfl_xor_sync(0xffffffffu, s1, off);
            s2 += __shfl_xor_sync(0xffffffffu, s2, off);
        }
        if (lane == 0) { sL[j] = s1; sD[j] = s2; }
    }
    __syncthreads();
    if (tid == 0) { float mx = -1e30f; for (int j=0;j<PDIM;++j) mx = fmaxf(mx, sL[j]); sred[0] = mx; }
    __syncthreads();
    if (tid < PDIM) sL[tid] = __expf(sL[tid] - sred[0]);
    __syncthreads();
    if (tid == 0) { float s = 0.f; for (int j=0;j<PDIM;++j) s += sL[j]; sred[1] = 1.0f/s; }
    __syncthreads();
    if (tid < PDIM) sL[tid] = sL[tid]*sred[1]*sD[tid] + g_D2[bn*PDIM + tid];
    __syncthreads();
    if (tid == 0) { float mx = -1e30f; for (int j=0;j<PDIM;++j) mx = fmaxf(mx, sL[j]); sred[0] = mx; }
    __syncthreads();
    if (tid < PDIM) sL[tid] = __expf(sL[tid] - sred[0]);
    __syncthreads();
    if (tid == 0) { float s = 0.f; for (int j=0;j<PDIM;++j) s += sL[j]; sred[1] = 1.0f/s; }
    __syncthreads();
    if (tid < PDIM) g_gw[(size_t)blk*PDIM + tid] = sL[tid]*sred[1];
}

// ===========================================================================
// K6: img_ws + assemble cii (fp32) + bf16 split of cii
// ===========================================================================
__global__ void imgws_kernel(const float* __restrict__ img)
{
    int chunk = blockIdx.x, bn = blockIdx.y, tid = threadIdx.x;
    __shared__ float sg[PDIM*PDIM];
    for (int t = tid; t < PDIM*PDIM; t += 256) sg[t] = g_gw[(size_t)bn*PDIM*PDIM + t];
    __syncthreads();

    int f = chunk*256 + tid;
    float acc[PDIM];
#pragma unroll
    for (int i = 0; i < PDIM; ++i) acc[i] = 0.f;
    const float* ib = img + (size_t)bn*PDIM*IMGF + f;
#pragma unroll 4
    for (int j = 0; j < PDIM; ++j) {
        float vj = ib[(size_t)j*IMGF];
#pragma unroll
        for (int i = 0; i < PDIM; ++i) acc[i] += sg[i*PDIM + j] * vj;
    }
    size_t cb = (size_t)bn*PDIM*F2 + f;
#pragma unroll
    for (int i = 0; i < PDIM; ++i) {
        float iv = ib[(size_t)i*IMGF];
        size_t o0 = cb + (size_t)i*F2;
        size_t o1 = o0 + IMGF;
        g_cii[o0] = iv;
        g_cii[o1] = acc[i];
        __nv_bfloat16 h, l;
        split2(iv, h, l);     g_cAh[o0] = h; g_cAl[o0] = l;
        split2(acc[i], h, l); g_cAh[o1] = h; g_cAl[o1] = l;
    }
}

// ===========================================================================
// Launch — single stream (multi-stream does NOT overlap under this harness)
// ===========================================================================
extern "C" void kernel_launch(void* const* d_in, const int* in_sizes, int n_in,
                              void* d_out, int out_size)
{
    const float* relation = (const float*)d_in[0];
    const float* img      = (const float*)d_in[1];
    const float* ques     = (const float*)d_in[2];
    const float* Wcr      = (const float*)d_in[3];
    const float* bcr      = (const float*)d_in[4];
    const float* Wq       = (const float*)d_in[5];
    const float* bq       = (const float*)d_in[6];
    const float* Wrw      = (const float*)d_in[7];
    const float* Wc       = (const float*)d_in[9];
    const float* bc       = (const float*)d_in[10];
    const float* Wg       = (const float*)d_in[11];
    const float* Ww       = (const float*)d_in[13];
    const float* bw       = (const float*)d_in[14];
    const float* Wi       = (const float*)d_in[15];
    const float* bi       = (const float*)d_in[16];
    float* out = (float*)d_out;

    cudaFuncSetAttribute(hgemm_gated, cudaFuncAttributeMaxDynamicSharedMemorySize, HG_SMEM);
    cudaFuncSetAttribute(hgemm_outk,  cudaFuncAttributeMaxDynamicSharedMemorySize, HG_SMEM);
    cudaFuncSetAttribute(hgemm_dual,  cudaFuncAttributeMaxDynamicSharedMemorySize, HG_SMEM);

    float *p_relC, *p_pimg, *p_pout, *p_cii;
    __nv_bfloat16 *p_rSh,*p_rSl,*p_iAh,*p_iAl,*p_cAh,*p_cAl,*p_gAh,*p_gAl;
    __nv_bfloat16 *p_B1h,*p_B1l,*p_B2h,*p_B2l,*p_Bwh,*p_Bwl,*p_Bih,*p_Bil;
    cudaGetSymbolAddress((void**)&p_relC, g_relC);
    cudaGetSymbolAddress((void**)&p_pimg, g_pimg);
    cudaGetSymbolAddress((void**)&p_pout, g_pout);
    cudaGetSymbolAddress((void**)&p_cii,  g_cii);
    cudaGetSymbolAddress((void**)&p_rSh, g_rSh); cudaGetSymbolAddress((void**)&p_rSl, g_rSl);
    cudaGetSymbolAddress((void**)&p_iAh, g_iAh); cudaGetSymbolAddress((void**)&p_iAl, g_iAl);
    cudaGetSymbolAddress((void**)&p_cAh, g_cAh); cudaGetSymbolAddress((void**)&p_cAl, g_cAl);
    cudaGetSymbolAddress((void**)&p_gAh, g_gAh); cudaGetSymbolAddress((void**)&p_gAl, g_gAl);
    cudaGetSymbolAddress((void**)&p_B1h, g_B1h); cudaGetSymbolAddress((void**)&p_B1l, g_B1l);
    cudaGetSymbolAddress((void**)&p_B2h, g_B2h); cudaGetSymbolAddress((void**)&p_B2l, g_B2l);
    cudaGetSymbolAddress((void**)&p_Bwh, g_Bwh); cudaGetSymbolAddress((void**)&p_Bwl, g_Bwl);
    cudaGetSymbolAddress((void**)&p_Bih, g_Bih); cudaGetSymbolAddress((void**)&p_Bil, g_Bil);

    // 1. all preprocessing (rels + ques + img split + weight tsplits) in ONE launch
    preprocess_all<<<PRE_TOTAL, 256>>>(relation, Wcr, bcr, ques, Wq, bq, Wrw, Wg,
                                       img, Wc, Ww, Wi);
    // 2. imgC split-K4 + relC GEMM merged (178 CTAs)
    hgemm_dual<<<178, GTHREADS, HG_SMEM>>>(p_iAh, p_iAl, p_B2h, p_B2l, p_pimg,
                                           p_rSh, p_rSl, p_B1h, p_B1l, p_relC);
    // 3. D2 fused with imgC reduce (imgC never materialized)
    d2_fused<<<ROWS, RELC>>>(bc);
    // 4. attention weights
    gw_kernel<<<ROWS, 128>>>();
    // 5. img_ws + cii (+ split)
    imgws_kernel<<<dim3(IMGF/256, BN), 256>>>(img);
    // 6. gated = sigmoid(cii@Ww + bw)*cii -> bf16 split  (384 CTAs, 64 chunks)
    hgemm_gated<<<dim3(F2/128, (ROWS+127)/128), GTHREADS, HG_SMEM>>>(
        p_cAh, p_cAl, p_Bwh, p_Bwl, bw, p_cii, p_gAh, p_gAl);
    // 7. out partials: split-K2 (384 CTAs, 32 chunks each)
    hgemm_outk<<<dim3(IMGF/128, (ROWS+127)/128, 2), GTHREADS, HG_SMEM>>>(
        p_gAh, p_gAl, p_Bih, p_Bil, p_pout);
    // 8. out = p0 + p1 + bi
    reduce_out<<<4096, 256>>>(bi, out);
}